// round 13
// baseline (speedup 1.0000x reference)
#include <cuda_runtime.h>
#include <math.h>

#define N 384
#define D 128
#define TPB 512            // 16 warps; sort width 512 (128 +inf pads)
#define NWARP (TPB / 32)
#define NTASK 78           // sum_{b=0..11} (12-b)
#define FULL 0xFFFFFFFFu

// Persistent accumulators. Zero at load; last block resets after finalizing so
// every invocation (correctness run + each graph replay) starts clean.
__device__ double   g_acc_trans = 0.0;
__device__ double   g_acc_hard  = 0.0;
__device__ unsigned g_done      = 0u;

__global__ __launch_bounds__(TPB) void rnc_main_kernel(
    const float* __restrict__ feat,   // [N, D]
    const float* __restrict__ rgreen, // [N, 3]
    const float* __restrict__ rred,   // [N, 3]
    const float* __restrict__ trans,  // [N, 3]
    const int*   __restrict__ sym,    // [N, 1]
    float*       __restrict__ out)
{
    __shared__ __align__(16) float fi[D];
    __shared__ __align__(16) float td_sh[N];
    __shared__ __align__(16) float rd_sh[N];
    __shared__ __align__(16) float l_sh[N];
    __shared__ __align__(16) float e_sh[N];
    __shared__ __align__(16) float rd_p[N];     // rd permuted to sorted order
    __shared__ __align__(16) float e_p[N];      // e  permuted to sorted order
    __shared__ __align__(16) float den_h_sh[N]; // accumulated den_hard per pos
    __shared__ __align__(16) unsigned long long key_sh[TPB];
    __shared__ float  wsum[NWARP];
    __shared__ double redt[NWARP];
    __shared__ double redh[NWARP];

    const int i    = blockIdx.x;
    const int tid  = threadIdx.x;
    const int lane = tid & 31;
    const int w    = tid >> 5;

    // ---- stage row-i feature vector (coalesced) ----
    if (tid < D / 4)
        reinterpret_cast<float4*>(fi)[tid] =
            reinterpret_cast<const float4*>(feat + i * D)[tid];
    __syncthreads();

    // ---- feature sq-dist -> logits/e: 16 warps x 24 rows, warp-coop coalesced
    {
        const float4 a = reinterpret_cast<const float4*>(fi)[lane];
        const int rowbase = w * 24;
        float sq = 0.f;
        #pragma unroll 4
        for (int r = 0; r < 24; r++) {
            float4 b = reinterpret_cast<const float4*>(feat + (rowbase + r) * D)[lane];
            float d0 = a.x - b.x, d1 = a.y - b.y, d2 = a.z - b.z, d3 = a.w - b.w;
            float p = d0 * d0;
            p = fmaf(d1, d1, p);
            p = fmaf(d2, d2, p);
            p = fmaf(d3, d3, p);
            #pragma unroll
            for (int o = 16; o; o >>= 1) p += __shfl_xor_sync(FULL, p, o);
            if (lane == r) sq = p;
        }
        if (lane < 24) {
            // rowmax of logits is exactly 0 (logit_ii = -0.5*sqrt(0) bit-exact,
            // all others <= 0) -> no max pass needed.
            int row = rowbase + lane;
            float l = -((sq > 0.f) ? sqrtf(sq) : 0.f) * 0.5f;
            l_sh[row] = l;
            e_sh[row] = (row == i) ? 0.f : expf(l);  // zero diag == offdiag
        }
    }

    // ---- label diffs for j = tid (< N); build sort key ----
    unsigned long long key = 0xFFFFFFFFFFFFFFFFULL;   // +inf pad for tid >= N
    if (tid < N) {
        const int j = tid;
        float ti0 = trans[i*3+0], ti1 = trans[i*3+1], ti2 = trans[i*3+2]; // bcast
        float d0 = ti0 - trans[j*3+0];
        float d1 = ti1 - trans[j*3+1];
        float d2 = ti2 - trans[j*3+2];
        float a0 = fabsf(d0), a1 = fabsf(d1), a2 = fabsf(d2);
        float s = ((a0 < 1.f) ? 0.5f*d0*d0 : a0 - 0.5f)
                + ((a1 < 1.f) ? 0.5f*d1*d1 : a1 - 0.5f)
                + ((a2 < 1.f) ? 0.5f*d2*d2 : a2 - 0.5f);
        float tdv = s * (1.0f / 3.0f);
        td_sh[j] = tdv;

        const float EPSC = 1e-8f;
        float gi0 = rgreen[i*3+0], gi1 = rgreen[i*3+1], gi2 = rgreen[i*3+2];
        float ngi = fmaxf(sqrtf(gi0*gi0 + gi1*gi1 + gi2*gi2), EPSC);
        float gj0 = rgreen[j*3+0], gj1 = rgreen[j*3+1], gj2 = rgreen[j*3+2];
        float ngj = fmaxf(sqrtf(gj0*gj0 + gj1*gj1 + gj2*gj2), EPSC);
        float gd  = 1.0f - (gi0*gj0 + gi1*gj1 + gi2*gj2) / (ngi * ngj);

        float ri0 = rred[i*3+0], ri1 = rred[i*3+1], ri2 = rred[i*3+2];
        float nri = fmaxf(sqrtf(ri0*ri0 + ri1*ri1 + ri2*ri2), EPSC);
        float rj0 = rred[j*3+0], rj1 = rred[j*3+1], rj2 = rred[j*3+2];
        float nrj = fmaxf(sqrtf(rj0*rj0 + rj1*rj1 + rj2*rj2), EPSC);
        float rdd = 1.0f - (ri0*rj0 + ri1*rj1 + ri2*rj2) / (nri * nrj);

        bool psym = (sym[i] == 1) || (sym[j] == 1);
        rd_sh[j] = psym ? gd : gd + rdd;

        // key: td bits (non-negative float -> order-preserving) | index
        key = ((unsigned long long)__float_as_uint(tdv) << 32)
              | (unsigned long long)j;
    }

    // ---- hybrid bitonic sort, 512 register-held keys, ascending ----
    // jj < 32: intra-warp via shfl (no barrier). jj >= 32: via smem (2 barriers).
    for (int kk = 2; kk <= TPB; kk <<= 1) {
        for (int jj = kk >> 1; jj > 0; jj >>= 1) {
            unsigned long long other;
            if (jj >= 32) {
                __syncthreads();
                key_sh[tid] = key;
                __syncthreads();
                other = key_sh[tid ^ jj];
            } else {
                other = __shfl_xor_sync(FULL, key, jj);
            }
            bool up     = ((tid & kk) == 0);
            bool takeLo = (up == ((tid & jj) == 0));
            bool repl   = takeLo ? (other < key) : (other > key);
            key = repl ? other : key;
        }
    }
    __syncthreads();

    // ---- gather rd/e into sorted order; position p = tid (pads at p >= N) ----
    int   oj = -1;
    float e_own = 0.f;
    if (tid < N) {
        oj    = (int)(key & 0xFFFFFFFFULL);
        e_own = e_sh[oj];
        rd_p[tid] = rd_sh[oj];
        e_p[tid]  = e_own;
        den_h_sh[tid] = 0.f;
    }
    __syncthreads();

    // ---- suffix sum of e_p: den_trans[p] = sum_{q >= p} e_p[q] ----
    float den_t;
    {
        float pre = e_own;   // inclusive prefix within warp (pads contribute 0)
        #pragma unroll
        for (int o = 1; o < 32; o <<= 1) {
            float t = __shfl_up_sync(FULL, pre, o);
            if (lane >= o) pre += t;
        }
        float wtot = __shfl_sync(FULL, pre, 31);
        if (lane == 31) wsum[w] = pre;
        __syncthreads();
        float tail = 0.f;
        #pragma unroll
        for (int ww = 0; ww < NWARP; ww++) if (ww > w) tail += wsum[ww];
        den_t = tail + wtot - (pre - e_own);   // tail + in-warp inclusive suffix
    }

    // ---- den_hard via balanced task queue over the triangle ----
    // Task t -> (p-block b, k-chunk c): block b owns positions [32b, 32b+32),
    // its k-suffix is groups [8b, 96) split into (12-b) chunks of 8 groups.
    // All 16 warps round-robin the 78 tasks (max 5 each = 40 group-iters).
    {
        const float4* rd4 = reinterpret_cast<const float4*>(rd_p);
        const float4* e4  = reinterpret_cast<const float4*>(e_p);
        for (int t = w; t < NTASK; t += NWARP) {
            int b = 0, rem = t;
            while (rem >= 12 - b) { rem -= 12 - b; b++; }
            const int c  = rem;
            const int p  = 32 * b + lane;
            const float rdo = rd_p[p];
            const int g0 = 8 * b + 8 * c;
            float dh = 0.f, dh2 = 0.f;
            if (c == 0) {
                // first chunk of the block: q >= p check needed
                #pragma unroll
                for (int g = 0; g < 8; g++) {
                    int gg = g0 + g;
                    float4 rk = rd4[gg];
                    float4 ek = e4[gg];
                    int qb = 4 * gg;
                    if (qb + 0 >= p && rdo <= rk.x) dh  += ek.x;
                    if (qb + 1 >= p && rdo <= rk.y) dh2 += ek.y;
                    if (qb + 2 >= p && rdo <= rk.z) dh  += ek.z;
                    if (qb + 3 >= p && rdo <= rk.w) dh2 += ek.w;
                }
            } else {
                // q >= 32b+32 > p guaranteed
                #pragma unroll
                for (int g = 0; g < 8; g++) {
                    int gg = g0 + g;
                    float4 rk = rd4[gg];
                    float4 ek = e4[gg];
                    if (rdo <= rk.x) dh  += ek.x;
                    if (rdo <= rk.y) dh2 += ek.y;
                    if (rdo <= rk.z) dh  += ek.z;
                    if (rdo <= rk.w) dh2 += ek.w;
                }
            }
            atomicAdd(&den_h_sh[p], dh + dh2);
        }
    }
    __syncthreads();

    // ---- per-j log terms (skip diagonal j == i; pads contribute 0) ----
    double pos_t = 0.0, pos_h = 0.0;
    if (tid < N && oj != i) {
        float den_h = den_h_sh[tid];
        float l = l_sh[oj];
        pos_t = (double)(l - logf(den_t + 1e-7f));
        pos_h = (double)(l - logf(den_h + 1e-7f));
    }

    // ---- block reduction (double) ----
    #pragma unroll
    for (int o = 16; o; o >>= 1) {
        pos_t += __shfl_xor_sync(FULL, pos_t, o);
        pos_h += __shfl_xor_sync(FULL, pos_h, o);
    }
    if (lane == 0) { redt[w] = pos_t; redh[w] = pos_h; }
    __syncthreads();

    // ---- global accumulation + last-block finalize (self-resetting) ----
    if (tid == 0) {
        double at = 0.0, ah = 0.0;
        #pragma unroll
        for (int ww = 0; ww < NWARP; ww++) { at += redt[ww]; ah += redh[ww]; }
        atomicAdd(&g_acc_trans, at);
        atomicAdd(&g_acc_hard,  ah);
        __threadfence();
        unsigned ticket = atomicAdd(&g_done, 1u);
        if (ticket == (unsigned)(N - 1)) {
            double vt = atomicAdd(&g_acc_trans, 0.0);
            double vh = atomicAdd(&g_acc_hard,  0.0);
            const double denom = (double)N * (double)(N - 1);
            out[0] = (float)((-vh / denom) + 0.5 * (-vt / denom));
            g_acc_trans = 0.0;
            g_acc_hard  = 0.0;
            g_done      = 0u;
        }
    }
}

extern "C" void kernel_launch(void* const* d_in, const int* in_sizes, int n_in,
                              void* d_out, int out_size) {
    const float* feat   = (const float*)d_in[0];
    const float* rgreen = (const float*)d_in[1];
    const float* rred   = (const float*)d_in[2];
    const float* trans  = (const float*)d_in[3];
    const int*   sym    = (const int*)d_in[4];
    float* out = (float*)d_out;

    rnc_main_kernel<<<N, TPB>>>(feat, rgreen, rred, trans, sym, out);
}